// round 1
// baseline (speedup 1.0000x reference)
#include <cuda_runtime.h>
#include <cstdint>

#define GRID_DIM   128
#define U_PIX      8192
#define N_TRK      3000
#define M_NEIGH    16
#define T_SIG      400
#define ADC_SAMPLE 50
#define NBINS      200          // T_TOTAL / ADC_SAMPLE
#define GAIN       0.25f
#define PEDESTAL   74.0f
#define ADC_MAX    255.0f

// Scratch (allocation-free rule: __device__ globals)
__device__ int   g_lut[GRID_DIM * GRID_DIM];     // (y,x) -> unique pixel id, -1 = none
__device__ float g_acc[U_PIX * NBINS];           // per-pixel per-50-sample-bin sums

// ---------------------------------------------------------------------------
// Kernel 1: zero accumulator + invalidate LUT
// ---------------------------------------------------------------------------
__global__ void k_init() {
    int tid    = blockIdx.x * blockDim.x + threadIdx.x;
    int stride = gridDim.x * blockDim.x;
    for (int i = tid; i < GRID_DIM * GRID_DIM; i += stride) g_lut[i] = -1;
    for (int i = tid; i < U_PIX * NBINS;       i += stride) g_acc[i] = 0.0f;
}

// ---------------------------------------------------------------------------
// Kernel 2: scatter unique_pix into the LUT (coords are unique by construction)
// ---------------------------------------------------------------------------
__global__ void k_lut(const int* __restrict__ unique_pix) {
    int u = blockIdx.x * blockDim.x + threadIdx.x;
    if (u >= U_PIX) return;
    int c0 = unique_pix[2 * u];
    int c1 = unique_pix[2 * u + 1];
    g_lut[c0 * GRID_DIM + c1] = u;
}

// ---------------------------------------------------------------------------
// Kernel 3: one warp per (track, neighbor) pair.
// Signal spans <=9 bins of width 50; for each bin, warp sums the contiguous
// segment and lane 0 does one atomicAdd into the L2-resident accumulator.
// ---------------------------------------------------------------------------
__global__ void k_accum(const int*   __restrict__ neigh,
                        const float* __restrict__ sig,
                        const int*   __restrict__ starts) {
    int gwarp = (blockIdx.x * blockDim.x + threadIdx.x) >> 5;
    int lane  = threadIdx.x & 31;
    if (gwarp >= N_TRK * M_NEIGH) return;

    int n = gwarp / M_NEIGH;
    int m = gwarp - n * M_NEIGH;

    int c0 = neigh[(n * M_NEIGH + m) * 2];
    int c1 = neigh[(n * M_NEIGH + m) * 2 + 1];
    if (c0 < 0 || c1 < 0) return;                 // dead channel -> discard bucket

    int pid = g_lut[c0 * GRID_DIM + c1];
    if (pid < 0) return;                          // no match -> discard bucket

    const float* s = sig + (size_t)(n * M_NEIGH + m) * T_SIG;
    int start = starts[n];

    int b0   = start / ADC_SAMPLE;
    int bend = (start + T_SIG - 1) / ADC_SAMPLE;  // <= 199 since start <= 9600-1

    float* accrow = g_acc + (size_t)pid * NBINS;

    for (int b = b0; b <= bend; ++b) {
        int lo = b * ADC_SAMPLE - start;       if (lo < 0)     lo = 0;
        int hi = (b + 1) * ADC_SAMPLE - start; if (hi > T_SIG) hi = T_SIG;

        float v = 0.0f;
        int t = lo + lane;
        if (t < hi) v = s[t];
        t += 32;
        if (t < hi) v += s[t];                    // segment length <= 50

        #pragma unroll
        for (int o = 16; o > 0; o >>= 1)
            v += __shfl_xor_sync(0xffffffffu, v, o);

        if (lane == 0) atomicAdd(&accrow[b], v);
    }
}

// ---------------------------------------------------------------------------
// Kernel 4: one warp per pixel row — inclusive scan over 200 bins with carry,
// fused affine + clip, coalesced output write.
// ---------------------------------------------------------------------------
__global__ void k_final(float* __restrict__ out) {
    int gwarp = (blockIdx.x * blockDim.x + threadIdx.x) >> 5;
    int lane  = threadIdx.x & 31;
    if (gwarp >= U_PIX) return;

    const float* row  = g_acc + (size_t)gwarp * NBINS;
    float*       orow = out   + (size_t)gwarp * NBINS;

    float carry = 0.0f;
    #pragma unroll
    for (int c = 0; c < NBINS; c += 32) {
        int  idx = c + lane;
        float v = (idx < NBINS) ? row[idx] : 0.0f;

        // warp inclusive scan
        #pragma unroll
        for (int o = 1; o < 32; o <<= 1) {
            float u = __shfl_up_sync(0xffffffffu, v, o);
            if (lane >= o) v += u;
        }

        float cs = v + carry;
        if (idx < NBINS) {
            float a = fminf(fmaxf(cs * GAIN + PEDESTAL, 0.0f), ADC_MAX);
            orow[idx] = a;
        }
        carry += __shfl_sync(0xffffffffu, v, 31);
    }
}

// ---------------------------------------------------------------------------
// Launch
// ---------------------------------------------------------------------------
extern "C" void kernel_launch(void* const* d_in, const int* in_sizes, int n_in,
                              void* d_out, int out_size) {
    const int*   neigh  = (const int*)  d_in[0];   // (3000, 16, 2) int32
    const int*   upix   = (const int*)  d_in[1];   // (8192, 2) int32
    const float* sig    = (const float*)d_in[2];   // (3000, 16, 400) float32
    const int*   starts = (const int*)  d_in[3];   // (3000,) int32
    float*       out    = (float*)      d_out;     // (8192, 200) float32

    (void)in_sizes; (void)n_in; (void)out_size;

    // 1) init scratch
    k_init<<<2048, 256>>>();

    // 2) build LUT
    k_lut<<<(U_PIX + 255) / 256, 256>>>(upix);

    // 3) accumulate: one warp per (n, m) pair => 48000 warps
    {
        int total_warps = N_TRK * M_NEIGH;
        int threads = 256;
        int blocks  = (total_warps * 32 + threads - 1) / threads;
        k_accum<<<blocks, threads>>>(neigh, sig, starts);
    }

    // 4) finalize: one warp per pixel row => 8192 warps
    {
        int threads = 256;
        int blocks  = (U_PIX * 32 + threads - 1) / threads;
        k_final<<<blocks, threads>>>(out);
    }
}

// round 2
// speedup vs baseline: 1.4269x; 1.4269x over previous
#include <cuda_runtime.h>
#include <cstdint>

#define GRID_DIM   128
#define U_PIX      8192
#define N_TRK      3000
#define M_NEIGH    16
#define T_SIG      400
#define ADC_SAMPLE 50
#define NBINS      200          // T_TOTAL / ADC_SAMPLE
#define MAX_BINS   9            // ceil((400+49)/50) = 9 bins max per signal
#define GAIN       0.25f
#define PEDESTAL   74.0f
#define ADC_MAX    255.0f

// Scratch (allocation-free rule: __device__ globals)
__device__ int   g_lut[GRID_DIM * GRID_DIM];     // (y,x) -> unique pixel id, -1 = none
__device__ float g_acc[U_PIX * NBINS];           // per-pixel per-50-sample-bin sums

// ---------------------------------------------------------------------------
// Kernel 1: zero accumulator (vectorized) + invalidate LUT
// ---------------------------------------------------------------------------
__global__ void k_init() {
    int tid    = blockIdx.x * blockDim.x + threadIdx.x;
    int stride = gridDim.x * blockDim.x;
    for (int i = tid; i < GRID_DIM * GRID_DIM; i += stride) g_lut[i] = -1;
    float4* acc4 = reinterpret_cast<float4*>(g_acc);
    const int n4 = (U_PIX * NBINS) / 4;          // 200 % 4 == 0 -> exact
    for (int i = tid; i < n4; i += stride) acc4[i] = make_float4(0.f, 0.f, 0.f, 0.f);
}

// ---------------------------------------------------------------------------
// Kernel 2: scatter unique_pix into the LUT (coords are unique by construction)
// ---------------------------------------------------------------------------
__global__ void k_lut(const int2* __restrict__ unique_pix) {
    int u = blockIdx.x * blockDim.x + threadIdx.x;
    if (u >= U_PIX) return;
    int2 c = unique_pix[u];
    g_lut[c.x * GRID_DIM + c.y] = u;
}

// ---------------------------------------------------------------------------
// Kernel 3: one warp per (track, neighbor) pair, fully unrolled 9-bin version.
// All 18 loads issue up front (high MLP); the nine 5-stage butterfly reductions
// run as ONE 5-stage butterfly over a 9-register vector (ILP across bins);
// lanes 0..8 each issue one atomicAdd (parallel REDG).
// ---------------------------------------------------------------------------
__global__ void k_accum(const int2*  __restrict__ neigh,
                        const float* __restrict__ sig,
                        const int*   __restrict__ starts) {
    int gwarp = (blockIdx.x * blockDim.x + threadIdx.x) >> 5;
    int lane  = threadIdx.x & 31;
    if (gwarp >= N_TRK * M_NEIGH) return;

    int2 c = neigh[gwarp];
    if (c.x < 0) return;                          // dead channel -> discard

    int pid = g_lut[c.x * GRID_DIM + c.y];
    if (pid < 0) return;

    int n     = gwarp >> 4;                       // M_NEIGH = 16
    int start = starts[n];
    int b0    = start / ADC_SAMPLE;               // 0..191
    int rel0  = start - b0 * ADC_SAMPLE;          // 0..49

    const float* s = sig + (size_t)gwarp * T_SIG;

    // Per-bin segment partial sums: bin b0+i covers t in [i*50-rel0, (i+1)*50-rel0) ∩ [0,400)
    float v[MAX_BINS];
    #pragma unroll
    for (int i = 0; i < MAX_BINS; ++i) {
        int lo = i * ADC_SAMPLE - rel0;           if (lo < 0)     lo = 0;
        int hi = (i + 1) * ADC_SAMPLE - rel0;     if (hi > T_SIG) hi = T_SIG;
        int t  = lo + lane;
        float a = (t      < hi) ? s[t]      : 0.0f;
        float b = (t + 32 < hi) ? s[t + 32] : 0.0f;  // segment length <= 50
        v[i] = a + b;
    }

    // One butterfly over the whole 9-vector: 5 stages, 9 independent adds/stage
    #pragma unroll
    for (int o = 16; o > 0; o >>= 1) {
        #pragma unroll
        for (int i = 0; i < MAX_BINS; ++i)
            v[i] += __shfl_xor_sync(0xffffffffu, v[i], o);
    }

    // lane i owns bin i (constant-index register selection, no local mem)
    float mine = 0.0f;
    #pragma unroll
    for (int i = 0; i < MAX_BINS; ++i)
        if (lane == i) mine = v[i];

    if (lane < MAX_BINS)                          // b0+8 <= 199 always
        atomicAdd(&g_acc[(size_t)pid * NBINS + b0 + lane], mine);
}

// ---------------------------------------------------------------------------
// Kernel 4: one warp per pixel row. float4 loads; per-lane serial scan inside
// the vector, one warp scan of lane totals per 128-element chunk, carry across
// the 2 chunks. Fused affine + clip, vectorized coalesced write.
// ---------------------------------------------------------------------------
__global__ void k_final(float* __restrict__ out) {
    int gwarp = (blockIdx.x * blockDim.x + threadIdx.x) >> 5;
    int lane  = threadIdx.x & 31;
    if (gwarp >= U_PIX) return;

    const float4* row4 = reinterpret_cast<const float4*>(g_acc + (size_t)gwarp * NBINS);
    float4*       out4 = reinterpret_cast<float4*>(out + (size_t)gwarp * NBINS);

    float carry = 0.0f;
    #pragma unroll
    for (int it = 0; it < 2; ++it) {              // 2 chunks of 128 cover 200
        int  vi  = it * 32 + lane;
        bool act = (vi < NBINS / 4);              // chunk 1: lanes 0..17

        float4 x = act ? row4[vi] : make_float4(0.f, 0.f, 0.f, 0.f);

        // inclusive scan inside the vector
        x.y += x.x;  x.z += x.y;  x.w += x.z;
        float s = x.w;

        // warp inclusive scan of lane totals
        float inc = s;
        #pragma unroll
        for (int o = 1; o < 32; o <<= 1) {
            float u = __shfl_up_sync(0xffffffffu, inc, o);
            if (lane >= o) inc += u;
        }
        float base = carry + (inc - s);           // exclusive prefix + carry

        if (act) {
            float4 r;
            r.x = fminf(fmaxf((x.x + base) * GAIN + PEDESTAL, 0.0f), ADC_MAX);
            r.y = fminf(fmaxf((x.y + base) * GAIN + PEDESTAL, 0.0f), ADC_MAX);
            r.z = fminf(fmaxf((x.z + base) * GAIN + PEDESTAL, 0.0f), ADC_MAX);
            r.w = fminf(fmaxf((x.w + base) * GAIN + PEDESTAL, 0.0f), ADC_MAX);
            out4[vi] = r;
        }
        carry += __shfl_sync(0xffffffffu, inc, 31);
    }
}

// ---------------------------------------------------------------------------
// Launch
// ---------------------------------------------------------------------------
extern "C" void kernel_launch(void* const* d_in, const int* in_sizes, int n_in,
                              void* d_out, int out_size) {
    const int2*  neigh  = (const int2*) d_in[0];   // (3000, 16, 2) int32
    const int2*  upix   = (const int2*) d_in[1];   // (8192, 2) int32
    const float* sig    = (const float*)d_in[2];   // (3000, 16, 400) float32
    const int*   starts = (const int*)  d_in[3];   // (3000,) int32
    float*       out    = (float*)      d_out;     // (8192, 200) float32

    (void)in_sizes; (void)n_in; (void)out_size;

    k_init<<<1024, 256>>>();
    k_lut<<<(U_PIX + 255) / 256, 256>>>(upix);

    {
        int total_warps = N_TRK * M_NEIGH;         // 48000
        int threads = 256;
        int blocks  = (total_warps * 32 + threads - 1) / threads;
        k_accum<<<blocks, threads>>>(neigh, sig, starts);
    }
    {
        int threads = 256;
        int blocks  = (U_PIX * 32 + threads - 1) / threads;   // 1024
        k_final<<<blocks, threads>>>(out);
    }
}